// round 1
// baseline (speedup 1.0000x reference)
#include <cuda_runtime.h>
#include <cstdint>

// ---------------------------------------------------------------------------
// ExpertsChooseMaskedExpand — round 0 baseline
//
// Shapes (hardcoded, validated against metadata order):
//   x:        (4, 1024, 2048) f32      d_in[0]
//   combine:  (4, 1024, 4, 512) f32    d_in[1]
//   dispatch: (4, 1024, 4, 512) f32    d_in[2]
//   weight:   (8192, 2048) f32         d_in[3]   flat-reshaped to (4, 8192, 512)
//   bias:     (8192,) f32              d_in[4]
//   num_experts: int (=4)              d_in[5]   (ignored, hardcoded)
//   out:      (4, 1024, 8192) f32
//
// Pipeline:
//   K1: xd[b,e] (512x512)  = dispatch[b,:,e,:]^T @ x[b,:,e*512:(e+1)*512]   K=1024
//   K2: y [b,e] (512x8192) = xd[b,e] @ w[e]^T + bias                        K=512
//   K3: out[b] (1024x8192) = combine[b] (1024x2048) @ y[b] (2048x8192)      K=2048
// ---------------------------------------------------------------------------

#define BM 128
#define BN 128
#define BK 8
#define TM 8
#define TN 8
#define PAD 4
#define NTHREADS 256

// Scratch (allocation-free rule: __device__ globals)
__device__ float g_xd[16ull * 512 * 512];          //  16 MB  (b*4+e, c, i)
__device__ float g_y [16ull * 512 * 8192];         // 256 MB  (b*4+e, c, o)

// ---------------------------------------------------------------------------
// K1: A (K-major: A[k*2048 + m]), B (K-major: B[k*2048 + n]) -> C (512x512)
// ---------------------------------------------------------------------------
__global__ __launch_bounds__(NTHREADS)
void k1_dispatch(const float* __restrict__ x, const float* __restrict__ dmask)
{
    const int bz = blockIdx.z;            // b*4 + e
    const int b  = bz >> 2;
    const int e  = bz & 3;
    const int K  = 1024;

    const float* A  = dmask + (size_t)b * 1024 * 2048 + e * 512;  // (k,m) stride 2048
    const float* Bx = x     + (size_t)b * 1024 * 2048 + e * 512;  // (k,n) stride 2048
    float*       Cm = g_xd  + (size_t)bz * 512 * 512;

    __shared__ float As[BK][BM + PAD];
    __shared__ float Bs[BK][BN + PAD];

    const int tid = threadIdx.x;
    const int tx  = tid & 15;
    const int ty  = tid >> 4;
    const int m0  = blockIdx.y * BM;
    const int n0  = blockIdx.x * BN;

    // loader: row lk (0..7), 4 consecutive cols lm
    const int lk = tid >> 5;
    const int lm = (tid & 31) * 4;

    float acc[TM][TN] = {};

    for (int k0 = 0; k0 < K; k0 += BK) {
        float4 av = *(const float4*)(A  + (size_t)(k0 + lk) * 2048 + m0 + lm);
        float4 bv = *(const float4*)(Bx + (size_t)(k0 + lk) * 2048 + n0 + lm);
        *(float4*)&As[lk][lm] = av;
        *(float4*)&Bs[lk][lm] = bv;
        __syncthreads();
#pragma unroll
        for (int kk = 0; kk < BK; ++kk) {
            float a[TM], bb[TN];
#pragma unroll
            for (int i = 0; i < TM; ++i) a[i]  = As[kk][ty * TM + i];
#pragma unroll
            for (int j = 0; j < TN; ++j) bb[j] = Bs[kk][tx * TN + j];
#pragma unroll
            for (int i = 0; i < TM; ++i)
#pragma unroll
                for (int j = 0; j < TN; ++j) acc[i][j] += a[i] * bb[j];
        }
        __syncthreads();
    }

#pragma unroll
    for (int i = 0; i < TM; ++i) {
        float* cp = Cm + (size_t)(m0 + ty * TM + i) * 512 + n0 + tx * TN;
        float4 v0 = {acc[i][0], acc[i][1], acc[i][2], acc[i][3]};
        float4 v1 = {acc[i][4], acc[i][5], acc[i][6], acc[i][7]};
        *(float4*)cp       = v0;
        *(float4*)(cp + 4) = v1;
    }
}

// ---------------------------------------------------------------------------
// K2: A (M-major: A[m*512 + k]), B (N-major: B[n*512 + k]) -> C (512x8192) +bias
// ---------------------------------------------------------------------------
__global__ __launch_bounds__(NTHREADS)
void k2_expert(const float* __restrict__ weight, const float* __restrict__ bias)
{
    const int bz = blockIdx.z;            // b*4 + e
    const int e  = bz & 3;
    const int K  = 512;

    const float* A  = g_xd   + (size_t)bz * 512 * 512;          // (m,k) lda=512
    const float* Bw = weight + (size_t)e * 8192 * 512;          // (n,k) ldb=512
    float*       Cm = g_y    + (size_t)bz * 512 * 8192;

    __shared__ float As[BK][BM + PAD];
    __shared__ float Bs[BK][BN + PAD];

    const int tid = threadIdx.x;
    const int tx  = tid & 15;
    const int ty  = tid >> 4;
    const int m0  = blockIdx.y * BM;
    const int n0  = blockIdx.x * BN;

    // transposed loader: row (m or n) = tid>>1, k quad = (tid&1)*4
    const int lr = tid >> 1;
    const int lq = (tid & 1) * 4;

    float acc[TM][TN] = {};

    for (int k0 = 0; k0 < K; k0 += BK) {
        float4 av = *(const float4*)(A  + (size_t)(m0 + lr) * 512 + k0 + lq);
        float4 bv = *(const float4*)(Bw + (size_t)(n0 + lr) * 512 + k0 + lq);
        As[lq + 0][lr] = av.x; As[lq + 1][lr] = av.y;
        As[lq + 2][lr] = av.z; As[lq + 3][lr] = av.w;
        Bs[lq + 0][lr] = bv.x; Bs[lq + 1][lr] = bv.y;
        Bs[lq + 2][lr] = bv.z; Bs[lq + 3][lr] = bv.w;
        __syncthreads();
#pragma unroll
        for (int kk = 0; kk < BK; ++kk) {
            float a[TM], bb[TN];
#pragma unroll
            for (int i = 0; i < TM; ++i) a[i]  = As[kk][ty * TM + i];
#pragma unroll
            for (int j = 0; j < TN; ++j) bb[j] = Bs[kk][tx * TN + j];
#pragma unroll
            for (int i = 0; i < TM; ++i)
#pragma unroll
                for (int j = 0; j < TN; ++j) acc[i][j] += a[i] * bb[j];
        }
        __syncthreads();
    }

#pragma unroll
    for (int i = 0; i < TM; ++i) {
        float* cp = Cm + (size_t)(m0 + ty * TM + i) * 8192 + n0 + tx * TN;
        float4 v0, v1;
        v0.x = acc[i][0] + bias[n0 + tx * TN + 0];
        v0.y = acc[i][1] + bias[n0 + tx * TN + 1];
        v0.z = acc[i][2] + bias[n0 + tx * TN + 2];
        v0.w = acc[i][3] + bias[n0 + tx * TN + 3];
        v1.x = acc[i][4] + bias[n0 + tx * TN + 4];
        v1.y = acc[i][5] + bias[n0 + tx * TN + 5];
        v1.z = acc[i][6] + bias[n0 + tx * TN + 6];
        v1.w = acc[i][7] + bias[n0 + tx * TN + 7];
        *(float4*)cp       = v0;
        *(float4*)(cp + 4) = v1;
    }
}

// ---------------------------------------------------------------------------
// K3: A (M-major: A[m*2048 + k]), B (K-major: B[k*8192 + n]) -> C (1024x8192)
// ---------------------------------------------------------------------------
__global__ __launch_bounds__(NTHREADS)
void k3_combine(const float* __restrict__ combine, float* __restrict__ out)
{
    const int b = blockIdx.z;
    const int K = 2048;

    const float* A  = combine + (size_t)b * 1024 * 2048;   // (m,k) lda=2048
    const float* By = g_y     + (size_t)b * 2048 * 8192;   // (k,n) ldb=8192
    float*       Cm = out     + (size_t)b * 1024 * 8192;

    __shared__ float As[BK][BM + PAD];
    __shared__ float Bs[BK][BN + PAD];

    const int tid = threadIdx.x;
    const int tx  = tid & 15;
    const int ty  = tid >> 4;
    const int m0  = blockIdx.y * BM;
    const int n0  = blockIdx.x * BN;

    // A: transposed loader; B: direct k-major loader
    const int lr = tid >> 1;
    const int lq = (tid & 1) * 4;
    const int lk = tid >> 5;
    const int lm = (tid & 31) * 4;

    float acc[TM][TN] = {};

    for (int k0 = 0; k0 < K; k0 += BK) {
        float4 av = *(const float4*)(A  + (size_t)(m0 + lr) * 2048 + k0 + lq);
        float4 bv = *(const float4*)(By + (size_t)(k0 + lk) * 8192 + n0 + lm);
        As[lq + 0][lr] = av.x; As[lq + 1][lr] = av.y;
        As[lq + 2][lr] = av.z; As[lq + 3][lr] = av.w;
        *(float4*)&Bs[lk][lm] = bv;
        __syncthreads();
#pragma unroll
        for (int kk = 0; kk < BK; ++kk) {
            float a[TM], bb[TN];
#pragma unroll
            for (int i = 0; i < TM; ++i) a[i]  = As[kk][ty * TM + i];
#pragma unroll
            for (int j = 0; j < TN; ++j) bb[j] = Bs[kk][tx * TN + j];
#pragma unroll
            for (int i = 0; i < TM; ++i)
#pragma unroll
                for (int j = 0; j < TN; ++j) acc[i][j] += a[i] * bb[j];
        }
        __syncthreads();
    }

#pragma unroll
    for (int i = 0; i < TM; ++i) {
        float* cp = Cm + (size_t)(m0 + ty * TM + i) * 8192 + n0 + tx * TN;
        float4 v0 = {acc[i][0], acc[i][1], acc[i][2], acc[i][3]};
        float4 v1 = {acc[i][4], acc[i][5], acc[i][6], acc[i][7]};
        *(float4*)cp       = v0;
        *(float4*)(cp + 4) = v1;
    }
}

// ---------------------------------------------------------------------------
extern "C" void kernel_launch(void* const* d_in, const int* in_sizes, int n_in,
                              void* d_out, int out_size)
{
    const float* x       = (const float*)d_in[0];
    const float* combine = (const float*)d_in[1];
    const float* dmask   = (const float*)d_in[2];
    const float* weight  = (const float*)d_in[3];
    const float* bias    = (const float*)d_in[4];
    float*       out     = (float*)d_out;

    // K1: (512x512) x 16 batches
    {
        dim3 grid(512 / BN, 512 / BM, 16);
        k1_dispatch<<<grid, NTHREADS>>>(x, dmask);
    }
    // K2: (512x8192) x 16 batches
    {
        dim3 grid(8192 / BN, 512 / BM, 16);
        k2_expert<<<grid, NTHREADS>>>(weight, bias);
    }
    // K3: (1024x8192) x 4 batches
    {
        dim3 grid(8192 / BN, 1024 / BM, 4);
        k3_combine<<<grid, NTHREADS>>>(combine, out);
    }
}

// round 6
// speedup vs baseline: 3.3006x; 3.3006x over previous
#include <cuda_runtime.h>
#include <cstdint>

// ---------------------------------------------------------------------------
// ExpertsChooseMaskedExpand — round 3: tf32 mma.sync (generic PTX, sm_103-legal)
//
//   K1: xd[b,e] (512x512)  = dispatch[b,:,e,:]^T @ x[b,:,e*512:]   K=1024
//   K2: y [b,e] (512x8192) = xd[b,e] @ w[e]^T + bias               K=512
//   K3: out[b] (1024x8192) = combine[b] @ y[b]                     K=2048
//
// One templated GEMM: CTA tile 128x128, K-chunk 32, 8 warps (warp tile 64x32),
// m16n8k8 tf32 mma.sync, ldmatrix fragment loads from XOR-swizzled smem,
// double-buffered tiles with register-prefetch LDG overlap.
// ---------------------------------------------------------------------------

#define NTHREADS   256
#define BM         128
#define BN         128
#define BKT        32
#define TILE_BYTES 16384            // 128 rows x 32 f32 (128 B/row)

__device__ float g_xd[16ull * 512 * 512];     //  16 MB scratch
__device__ float g_y [16ull * 512 * 8192];    // 256 MB scratch

// ---------------------------------------------------------------- helpers --
__device__ __forceinline__ uint32_t smem_u32(const void* p) {
    uint32_t a;
    asm("{ .reg .u64 t; cvta.to.shared.u64 t, %1; cvt.u32.u64 %0, t; }"
        : "=r"(a) : "l"(p));
    return a;
}
__device__ __forceinline__ uint32_t f2tf32(float x) {
    uint32_t r;
    asm("cvt.rna.tf32.f32 %0, %1;" : "=r"(r) : "f"(x));
    return r;
}
// tile rows are 128 B = 8 x 16B columns; swizzle col16 ^= (row & 7)
__device__ __forceinline__ int swz_off(int row, int byte_in_row) {
    const int c16 = byte_in_row >> 4;
    const int sub = byte_in_row & 15;
    return row * 128 + (((c16 ^ (row & 7)) << 4) | sub);
}

#define LDSM_X4(r0, r1, r2, r3, addr)                                          \
    asm volatile("ldmatrix.sync.aligned.m8n8.x4.shared.b16 {%0,%1,%2,%3}, [%4];" \
                 : "=r"(r0), "=r"(r1), "=r"(r2), "=r"(r3) : "r"(addr))

#define MMA_TF32(c, a, b0v, b1v)                                               \
    asm volatile("mma.sync.aligned.m16n8k8.row.col.f32.tf32.tf32.f32 "         \
                 "{%0,%1,%2,%3}, {%4,%5,%6,%7}, {%8,%9}, {%0,%1,%2,%3};"       \
                 : "+f"((c)[0]), "+f"((c)[1]), "+f"((c)[2]), "+f"((c)[3])      \
                 : "r"((a)[0]), "r"((a)[1]), "r"((a)[2]), "r"((a)[3]),         \
                   "r"(b0v), "r"(b1v))

// ---------------------------------------------------------------- loaders --
// Each thread moves 16 floats per 128x32 tile.
// KC=true : source S[r*ld + k]  (k-contiguous rows)
// KC=false: source S[k*ld + r]  (transpose on the fly)
template <bool KC>
__device__ __forceinline__ void ldg_tile(const float* __restrict__ S, long ld,
                                         int tid, float v[16]) {
    if (KC) {
        const int q  = tid & 7;       // 16B column
        const int r0 = tid >> 3;      // 0..31
#pragma unroll
        for (int i = 0; i < 4; ++i)
            *(float4*)(v + 4 * i) =
                *(const float4*)(S + (long)(r0 + 32 * i) * ld + q * 4);
    } else {
        const int r   = tid & 127;
        const int kq0 = (tid >> 7) * 4;
#pragma unroll
        for (int i = 0; i < 4; ++i) {
            const int k = kq0 + 8 * i;
#pragma unroll
            for (int j = 0; j < 4; ++j)
                v[4 * i + j] = S[(long)(k + j) * ld + r];
        }
    }
}
template <bool KC>
__device__ __forceinline__ void sts_tile(char* tile, int tid, const float v[16]) {
    if (KC) {
        const int q  = tid & 7;
        const int r0 = tid >> 3;
#pragma unroll
        for (int i = 0; i < 4; ++i) {
            uint4 w;
            w.x = f2tf32(v[4 * i + 0]); w.y = f2tf32(v[4 * i + 1]);
            w.z = f2tf32(v[4 * i + 2]); w.w = f2tf32(v[4 * i + 3]);
            *(uint4*)(tile + swz_off(r0 + 32 * i, q * 16)) = w;
        }
    } else {
        const int r   = tid & 127;
        const int kq0 = (tid >> 7) * 4;
#pragma unroll
        for (int i = 0; i < 4; ++i) {
            const int k = kq0 + 8 * i;
            uint4 w;
            w.x = f2tf32(v[4 * i + 0]); w.y = f2tf32(v[4 * i + 1]);
            w.z = f2tf32(v[4 * i + 2]); w.w = f2tf32(v[4 * i + 3]);
            *(uint4*)(tile + swz_off(r, k * 4)) = w;
        }
    }
}

// ------------------------------------------------------------- mma engine --
// Warp tile 64x32: 4 m16 tiles x 4 n8 tiles. One K=32 chunk = 4 k8 steps.
__device__ __forceinline__ void mma_chunk(uint32_t As, uint32_t Bs,
                                          int wm, int wn, int lane,
                                          float (&acc)[4][4][4]) {
    const int mat  = lane >> 3;
    const int l7   = lane & 7;
    // A: rows (mat&1)*8 + l7, 16B-col offset (mat>>1)
    const int arow = (mat & 1) * 8 + l7;
    const int ac16 = (mat >> 1);
    // B: rows (mat>>1)*8 + l7, 16B-col offset (mat&1)
    const int brow = (mat >> 1) * 8 + l7;
    const int bc16 = (mat & 1);

#pragma unroll
    for (int ks = 0; ks < 4; ++ks) {
        uint32_t a[4][4];
#pragma unroll
        for (int mi = 0; mi < 4; ++mi) {
            const int row = wm * 64 + mi * 16 + arow;
            const uint32_t addr =
                As + row * 128 + (((ks * 2 + ac16) ^ l7) << 4);
            LDSM_X4(a[mi][0], a[mi][1], a[mi][2], a[mi][3], addr);
        }
        uint32_t b[2][4];
#pragma unroll
        for (int bi = 0; bi < 2; ++bi) {
            const int row = wn * 32 + bi * 16 + brow;
            const uint32_t addr =
                Bs + row * 128 + (((ks * 2 + bc16) ^ l7) << 4);
            LDSM_X4(b[bi][0], b[bi][1], b[bi][2], b[bi][3], addr);
        }
#pragma unroll
        for (int mi = 0; mi < 4; ++mi)
#pragma unroll
            for (int ni = 0; ni < 4; ++ni)
                MMA_TF32(acc[mi][ni], a[mi],
                         b[ni >> 1][(ni & 1) * 2], b[ni >> 1][(ni & 1) * 2 + 1]);
    }
}

// ------------------------------------------------------------------- body --
template <int KT, bool AKC, bool BKC, bool HASB>
__device__ __forceinline__ void gemm_body(const float* __restrict__ A, long ldA,
                                          const float* __restrict__ B, long ldB,
                                          const float* __restrict__ bias,
                                          float* __restrict__ C, long ldC) {
    extern __shared__ __align__(16) char dyn[];

    const int tid  = threadIdx.x;
    const int wid  = tid >> 5;
    const int lane = tid & 31;
    const int wm   = wid >> 2;     // 0..1
    const int wn   = wid & 3;      // 0..3
    const int m0   = blockIdx.y * BM;
    const int n0   = blockIdx.x * BN;

    // 128B-align tile base for clean swizzle
    const uint32_t dynb = smem_u32(dyn);
    const uint32_t base = (dynb + 127u) & ~127u;
    char* tiles = dyn + (base - dynb);

    float acc[4][4][4] = {};

    // prologue: chunk 0
    {
        const float* Ac = AKC ? (A + (long)m0 * ldA) : (A + m0);
        const float* Bc = BKC ? (B + (long)n0 * ldB) : (B + n0);
        float va[16], vb[16];
        ldg_tile<AKC>(Ac, ldA, tid, va);
        ldg_tile<BKC>(Bc, ldB, tid, vb);
        sts_tile<AKC>(tiles, tid, va);
        sts_tile<BKC>(tiles + TILE_BYTES, tid, vb);
    }
    __syncthreads();

    const int NIT = KT / BKT;
    for (int it = 0; it < NIT; ++it) {
        const int cur = it & 1;
        const bool pf = (it + 1 < NIT);
        float va[16], vb[16];
        if (pf) {
            const long k0 = (long)(it + 1) * BKT;
            const float* Ac = AKC ? (A + (long)m0 * ldA + k0) : (A + k0 * ldA + m0);
            const float* Bc = BKC ? (B + (long)n0 * ldB + k0) : (B + k0 * ldB + n0);
            ldg_tile<AKC>(Ac, ldA, tid, va);
            ldg_tile<BKC>(Bc, ldB, tid, vb);
        }
        mma_chunk(base + cur * 2 * TILE_BYTES,
                  base + cur * 2 * TILE_BYTES + TILE_BYTES,
                  wm, wn, lane, acc);
        if (pf) {
            char* nxt = tiles + (cur ^ 1) * 2 * TILE_BYTES;
            sts_tile<AKC>(nxt, tid, va);
            sts_tile<BKC>(nxt + TILE_BYTES, tid, vb);
        }
        __syncthreads();
    }

    // epilogue: c0,c1 at (row, col..col+1), c2,c3 at (row+8, ...)
#pragma unroll
    for (int mi = 0; mi < 4; ++mi) {
        const int r0 = m0 + wm * 64 + mi * 16 + (lane >> 2);
#pragma unroll
        for (int ni = 0; ni < 4; ++ni) {
            const int c = n0 + wn * 32 + ni * 8 + (lane & 3) * 2;
            float2 v0 = {acc[mi][ni][0], acc[mi][ni][1]};
            float2 v1 = {acc[mi][ni][2], acc[mi][ni][3]};
            if (HASB) {
                const float b0 = __ldg(bias + c), b1 = __ldg(bias + c + 1);
                v0.x += b0; v0.y += b1;
                v1.x += b0; v1.y += b1;
            }
            *(float2*)(C + (long)r0 * ldC + c)       = v0;
            *(float2*)(C + (long)(r0 + 8) * ldC + c) = v1;
        }
    }
}

// ---------------------------------------------------------------- kernels --
__global__ __launch_bounds__(NTHREADS)
void k1_dispatch(const float* __restrict__ x, const float* __restrict__ dm) {
    const int bz = blockIdx.z, b = bz >> 2, e = bz & 3;
    gemm_body<1024, false, false, false>(
        dm + (long)b * 1024 * 2048 + e * 512, 2048,   // A: (k=t, m=c) m-contig
        x  + (long)b * 1024 * 2048 + e * 512, 2048,   // B: (k=t, n=i) n-contig
        nullptr,
        g_xd + (long)bz * 512 * 512, 512);
}
__global__ __launch_bounds__(NTHREADS)
void k2_expert(const float* __restrict__ w, const float* __restrict__ bias) {
    const int bz = blockIdx.z, e = bz & 3;
    gemm_body<512, true, true, true>(
        g_xd + (long)bz * 512 * 512, 512,             // A: (m=c, k=i) k-contig
        w + (long)e * 8192 * 512, 512,                // B: (n=o, k=i) k-contig
        bias,
        g_y + (long)bz * 512 * 8192, 8192);
}
__global__ __launch_bounds__(NTHREADS)
void k3_combine(const float* __restrict__ cmb, float* __restrict__ out) {
    const int b = blockIdx.z;
    gemm_body<2048, true, false, false>(
        cmb + (long)b * 1024 * 2048, 2048,            // A: (m=t, k=ec) k-contig
        g_y + (long)b * 2048 * 8192, 8192,            // B: (k=ec, n=o) n-contig
        nullptr,
        out + (long)b * 1024 * 8192, 8192);
}

// ----------------------------------------------------------------- launch --
extern "C" void kernel_launch(void* const* d_in, const int* in_sizes, int n_in,
                              void* d_out, int out_size) {
    const float* x       = (const float*)d_in[0];
    const float* combine = (const float*)d_in[1];
    const float* dmask   = (const float*)d_in[2];
    const float* weight  = (const float*)d_in[3];
    const float* bias    = (const float*)d_in[4];
    float*       out     = (float*)d_out;

    const int SMEM = 4 * TILE_BYTES + 256;   // 2 double-buffered A+B tiles
    cudaFuncSetAttribute(k1_dispatch, cudaFuncAttributeMaxDynamicSharedMemorySize, SMEM);
    cudaFuncSetAttribute(k2_expert,   cudaFuncAttributeMaxDynamicSharedMemorySize, SMEM);
    cudaFuncSetAttribute(k3_combine,  cudaFuncAttributeMaxDynamicSharedMemorySize, SMEM);

    k1_dispatch<<<dim3(512 / BN, 512 / BM, 16),  NTHREADS, SMEM>>>(x, dmask);
    k2_expert  <<<dim3(8192 / BN, 512 / BM, 16), NTHREADS, SMEM>>>(weight, bias);
    k3_combine <<<dim3(8192 / BN, 1024 / BM, 4), NTHREADS, SMEM>>>(combine, out);
}

// round 7
// speedup vs baseline: 3.8328x; 1.1612x over previous
#include <cuda_runtime.h>
#include <cstdint>

// ---------------------------------------------------------------------------
// ExpertsChooseMaskedExpand — round 7: tf32 mma.sync, STS-early pipeline
//
//   K1: xd[b,e] (512x512)  = dispatch[b,:,e,:]^T @ x[b,:,e*512:]   K=1024
//   K2: y [b,e] (512x8192) = xd[b,e] @ w[e]^T + bias               K=512
//   K3: out[b] (1024x8192) = combine[b] @ y[b]                     K=2048
//
// CTA tile 128x128, K-chunk 32, 8 warps (warp tile 64x32), m16n8k8 tf32.
// Schedule per chunk: STS(next buf, data LDG'd last iter) -> MMA(cur buf)
// -> LDG(chunk it+2 into regs) -> sync. The cvt+STS work overlaps other
// warps' HMMA issue instead of trailing it.
// ---------------------------------------------------------------------------

#define NTHREADS   256
#define BM         128
#define BN         128
#define BKT        32
#define TILE_BYTES 16384            // 128 rows x 32 f32 (128 B/row)

__device__ float g_xd[16ull * 512 * 512];     //  16 MB scratch
__device__ float g_y [16ull * 512 * 8192];    // 256 MB scratch

// ---------------------------------------------------------------- helpers --
__device__ __forceinline__ uint32_t smem_u32(const void* p) {
    uint32_t a;
    asm("{ .reg .u64 t; cvta.to.shared.u64 t, %1; cvt.u32.u64 %0, t; }"
        : "=r"(a) : "l"(p));
    return a;
}
__device__ __forceinline__ uint32_t f2tf32(float x) {
    uint32_t r;
    asm("cvt.rna.tf32.f32 %0, %1;" : "=r"(r) : "f"(x));
    return r;
}
// tile rows are 128 B = 8 x 16B columns; swizzle col16 ^= (row & 7)
__device__ __forceinline__ int swz_off(int row, int byte_in_row) {
    const int c16 = byte_in_row >> 4;
    const int sub = byte_in_row & 15;
    return row * 128 + (((c16 ^ (row & 7)) << 4) | sub);
}

#define LDSM_X4(r0, r1, r2, r3, addr)                                          \
    asm volatile("ldmatrix.sync.aligned.m8n8.x4.shared.b16 {%0,%1,%2,%3}, [%4];" \
                 : "=r"(r0), "=r"(r1), "=r"(r2), "=r"(r3) : "r"(addr))

#define MMA_TF32(c, a, b0v, b1v)                                               \
    asm volatile("mma.sync.aligned.m16n8k8.row.col.f32.tf32.tf32.f32 "         \
                 "{%0,%1,%2,%3}, {%4,%5,%6,%7}, {%8,%9}, {%0,%1,%2,%3};"       \
                 : "+f"((c)[0]), "+f"((c)[1]), "+f"((c)[2]), "+f"((c)[3])      \
                 : "r"((a)[0]), "r"((a)[1]), "r"((a)[2]), "r"((a)[3]),         \
                   "r"(b0v), "r"(b1v))

// ---------------------------------------------------------------- loaders --
// Each thread moves 16 floats per 128x32 tile.
// KC=true : source S[r*ld + k]  (k-contiguous rows)
// KC=false: source S[k*ld + r]  (transpose on the fly)
template <bool KC>
__device__ __forceinline__ void ldg_tile(const float* __restrict__ S, long ld,
                                         int tid, float v[16]) {
    if (KC) {
        const int q  = tid & 7;       // 16B column
        const int r0 = tid >> 3;      // 0..31
#pragma unroll
        for (int i = 0; i < 4; ++i)
            *(float4*)(v + 4 * i) =
                *(const float4*)(S + (long)(r0 + 32 * i) * ld + q * 4);
    } else {
        const int r   = tid & 127;
        const int kq0 = (tid >> 7) * 4;
#pragma unroll
        for (int i = 0; i < 4; ++i) {
            const int k = kq0 + 8 * i;
#pragma unroll
            for (int j = 0; j < 4; ++j)
                v[4 * i + j] = S[(long)(k + j) * ld + r];
        }
    }
}
template <bool KC>
__device__ __forceinline__ void sts_tile(char* tile, int tid, const float v[16]) {
    if (KC) {
        const int q  = tid & 7;
        const int r0 = tid >> 3;
#pragma unroll
        for (int i = 0; i < 4; ++i) {
            uint4 w;
            w.x = f2tf32(v[4 * i + 0]); w.y = f2tf32(v[4 * i + 1]);
            w.z = f2tf32(v[4 * i + 2]); w.w = f2tf32(v[4 * i + 3]);
            *(uint4*)(tile + swz_off(r0 + 32 * i, q * 16)) = w;
        }
    } else {
        const int r   = tid & 127;
        const int kq0 = (tid >> 7) * 4;
#pragma unroll
        for (int i = 0; i < 4; ++i) {
            const int k = kq0 + 8 * i;
            uint4 w;
            w.x = f2tf32(v[4 * i + 0]); w.y = f2tf32(v[4 * i + 1]);
            w.z = f2tf32(v[4 * i + 2]); w.w = f2tf32(v[4 * i + 3]);
            *(uint4*)(tile + swz_off(r, k * 4)) = w;
        }
    }
}

// ------------------------------------------------------------- mma engine --
// Warp tile 64x32: 4 m16 tiles x 4 n8 tiles. One K=32 chunk = 4 k8 steps.
__device__ __forceinline__ void mma_chunk(uint32_t As, uint32_t Bs,
                                          int wm, int wn, int lane,
                                          float (&acc)[4][4][4]) {
    const int mat  = lane >> 3;
    const int l7   = lane & 7;
    const int arow = (mat & 1) * 8 + l7;
    const int ac16 = (mat >> 1);
    const int brow = (mat >> 1) * 8 + l7;
    const int bc16 = (mat & 1);

    // hoisted per-warp row bases
    uint32_t abase[4], bbase[2];
#pragma unroll
    for (int mi = 0; mi < 4; ++mi)
        abase[mi] = As + (wm * 64 + mi * 16 + arow) * 128;
#pragma unroll
    for (int bi = 0; bi < 2; ++bi)
        bbase[bi] = Bs + (wn * 32 + bi * 16 + brow) * 128;

#pragma unroll
    for (int ks = 0; ks < 4; ++ks) {
        const uint32_t acol = ((ks * 2 + ac16) ^ l7) << 4;
        const uint32_t bcol = ((ks * 2 + bc16) ^ l7) << 4;
        uint32_t a[4][4];
#pragma unroll
        for (int mi = 0; mi < 4; ++mi)
            LDSM_X4(a[mi][0], a[mi][1], a[mi][2], a[mi][3], abase[mi] + acol);
        uint32_t b[2][4];
#pragma unroll
        for (int bi = 0; bi < 2; ++bi)
            LDSM_X4(b[bi][0], b[bi][1], b[bi][2], b[bi][3], bbase[bi] + bcol);
#pragma unroll
        for (int mi = 0; mi < 4; ++mi)
#pragma unroll
            for (int ni = 0; ni < 4; ++ni)
                MMA_TF32(acc[mi][ni], a[mi],
                         b[ni >> 1][(ni & 1) * 2], b[ni >> 1][(ni & 1) * 2 + 1]);
    }
}

// ------------------------------------------------------------------- body --
template <int KT, bool AKC, bool BKC, bool HASB>
__device__ __forceinline__ void gemm_body(const float* __restrict__ A, long ldA,
                                          const float* __restrict__ B, long ldB,
                                          const float* __restrict__ bias,
                                          float* __restrict__ C, long ldC) {
    extern __shared__ __align__(16) char dyn[];

    const int tid  = threadIdx.x;
    const int wid  = tid >> 5;
    const int lane = tid & 31;
    const int wm   = wid >> 2;     // 0..1
    const int wn   = wid & 3;      // 0..3
    const int m0   = blockIdx.y * BM;
    const int n0   = blockIdx.x * BN;

    const uint32_t dynb = smem_u32(dyn);
    const uint32_t base = (dynb + 127u) & ~127u;
    char* tiles = dyn + (base - dynb);

    float acc[4][4][4] = {};
    float va[16], vb[16];

    // chunk-k source pointers
    auto aptr = [&](long k0) {
        return AKC ? (A + (long)m0 * ldA + k0) : (A + k0 * ldA + m0);
    };
    auto bptr = [&](long k0) {
        return BKC ? (B + (long)n0 * ldB + k0) : (B + k0 * ldB + n0);
    };

    // prologue: chunk 0 -> buf0; then prefetch chunk 1 into regs
    ldg_tile<AKC>(aptr(0), ldA, tid, va);
    ldg_tile<BKC>(bptr(0), ldB, tid, vb);
    sts_tile<AKC>(tiles, tid, va);
    sts_tile<BKC>(tiles + TILE_BYTES, tid, vb);
    __syncthreads();

    const int NIT = KT / BKT;
    if (NIT > 1) {
        ldg_tile<AKC>(aptr(BKT), ldA, tid, va);
        ldg_tile<BKC>(bptr(BKT), ldB, tid, vb);
    }

    for (int it = 0; it < NIT; ++it) {
        const int cur = it & 1;
        // 1) store chunk it+1 (regs -> other buffer) BEFORE the MMA phase;
        //    readers of that buffer finished at sync(it-1).
        if (it + 1 < NIT) {
            char* nxt = tiles + (cur ^ 1) * 2 * TILE_BYTES;
            sts_tile<AKC>(nxt, tid, va);
            sts_tile<BKC>(nxt + TILE_BYTES, tid, vb);
        }
        // 2) MMA on current buffer (tensor pipe stays dense while other
        //    warps drain their cvt/STS)
        mma_chunk(base + cur * 2 * TILE_BYTES,
                  base + cur * 2 * TILE_BYTES + TILE_BYTES,
                  wm, wn, lane, acc);
        // 3) prefetch chunk it+2 into regs; latency hidden by next iteration
        if (it + 2 < NIT) {
            const long k0 = (long)(it + 2) * BKT;
            ldg_tile<AKC>(aptr(k0), ldA, tid, va);
            ldg_tile<BKC>(bptr(k0), ldB, tid, vb);
        }
        __syncthreads();
    }

    // epilogue: c0,c1 at (row, col..col+1), c2,c3 at (row+8, ...)
#pragma unroll
    for (int mi = 0; mi < 4; ++mi) {
        const int r0 = m0 + wm * 64 + mi * 16 + (lane >> 2);
#pragma unroll
        for (int ni = 0; ni < 4; ++ni) {
            const int c = n0 + wn * 32 + ni * 8 + (lane & 3) * 2;
            float2 v0 = {acc[mi][ni][0], acc[mi][ni][1]};
            float2 v1 = {acc[mi][ni][2], acc[mi][ni][3]};
            if (HASB) {
                const float b0 = __ldg(bias + c), b1 = __ldg(bias + c + 1);
                v0.x += b0; v0.y += b1;
                v1.x += b0; v1.y += b1;
            }
            *(float2*)(C + (long)r0 * ldC + c)       = v0;
            *(float2*)(C + (long)(r0 + 8) * ldC + c) = v1;
        }
    }
}

// ---------------------------------------------------------------- kernels --
__global__ __launch_bounds__(NTHREADS, 2)
void k1_dispatch(const float* __restrict__ x, const float* __restrict__ dm) {
    const int bz = blockIdx.z, b = bz >> 2, e = bz & 3;
    gemm_body<1024, false, false, false>(
        dm + (long)b * 1024 * 2048 + e * 512, 2048,   // A: (k=t, m=c) m-contig
        x  + (long)b * 1024 * 2048 + e * 512, 2048,   // B: (k=t, n=i) n-contig
        nullptr,
        g_xd + (long)bz * 512 * 512, 512);
}
__global__ __launch_bounds__(NTHREADS, 2)
void k2_expert(const float* __restrict__ w, const float* __restrict__ bias) {
    const int bz = blockIdx.z, e = bz & 3;
    gemm_body<512, true, true, true>(
        g_xd + (long)bz * 512 * 512, 512,             // A: (m=c, k=i) k-contig
        w + (long)e * 8192 * 512, 512,                // B: (n=o, k=i) k-contig
        bias,
        g_y + (long)bz * 512 * 8192, 8192);
}
__global__ __launch_bounds__(NTHREADS, 2)
void k3_combine(const float* __restrict__ cmb, float* __restrict__ out) {
    const int b = blockIdx.z;
    gemm_body<2048, true, false, false>(
        cmb + (long)b * 1024 * 2048, 2048,            // A: (m=t, k=ec) k-contig
        g_y + (long)b * 2048 * 8192, 8192,            // B: (k=ec, n=o) n-contig
        nullptr,
        out + (long)b * 1024 * 8192, 8192);
}

// ----------------------------------------------------------------- launch --
extern "C" void kernel_launch(void* const* d_in, const int* in_sizes, int n_in,
                              void* d_out, int out_size) {
    const float* x       = (const float*)d_in[0];
    const float* combine = (const float*)d_in[1];
    const float* dmask   = (const float*)d_in[2];
    const float* weight  = (const float*)d_in[3];
    const float* bias    = (const float*)d_in[4];
    float*       out     = (float*)d_out;

    const int SMEM = 4 * TILE_BYTES + 256;
    cudaFuncSetAttribute(k1_dispatch, cudaFuncAttributeMaxDynamicSharedMemorySize, SMEM);
    cudaFuncSetAttribute(k2_expert,   cudaFuncAttributeMaxDynamicSharedMemorySize, SMEM);
    cudaFuncSetAttribute(k3_combine,  cudaFuncAttributeMaxDynamicSharedMemorySize, SMEM);

    k1_dispatch<<<dim3(512 / BN, 512 / BM, 16),  NTHREADS, SMEM>>>(x, dmask);
    k2_expert  <<<dim3(8192 / BN, 512 / BM, 16), NTHREADS, SMEM>>>(weight, bias);
    k3_combine <<<dim3(8192 / BN, 1024 / BM, 4), NTHREADS, SMEM>>>(combine, out);
}

// round 9
// speedup vs baseline: 5.5431x; 1.4462x over previous
#include <cuda_runtime.h>
#include <cstdint>

// ---------------------------------------------------------------------------
// ExpertsChooseMaskedExpand — round 8 (resubmit): algebraic reassociation
//
//   out = combine @ ((dispatch^T x) @ W^T + bias)
//       = (combine @ (dispatch^T x)) @ W^T + bias * rowsum(combine)
//
//   K1: xd[b,e] (512x512)   = dispatch[b,:,e,:]^T @ x[b,:,e*512:]   8.6 GF
//   RS: s[b,t]              = sum_{e,c} combine[b,t,e,c]            (tiny)
//   K2: z[b] (1024x2048)    = combine_e @ xd_e  (per e slice)       8.6 GF
//   K3: out[b] (1024x8192)  = z[b] @ Wseg^T + bias*s              137.4 GF
//
// Total 154.6 GF (was 214.7). Same tf32 mma.sync engine: CTA 128x128,
// K-chunk 32, 8 warps (64x32), STS-early double-buffered pipeline.
// ---------------------------------------------------------------------------

#define NTHREADS   256
#define BM         128
#define BN         128
#define BKT        32
#define TILE_BYTES 16384            // 128 rows x 32 f32 (128 B/row)

__device__ float g_xd[16ull * 512 * 512];     // 16 MB  (b*4+e, c, i)
__device__ float g_z [4ull * 1024 * 2048];    // 32 MB  (b, t, e*512+i)
__device__ float g_s [4 * 1024];              // rowsum of combine

// ---------------------------------------------------------------- helpers --
__device__ __forceinline__ uint32_t smem_u32(const void* p) {
    uint32_t a;
    asm("{ .reg .u64 t; cvta.to.shared.u64 t, %1; cvt.u32.u64 %0, t; }"
        : "=r"(a) : "l"(p));
    return a;
}
__device__ __forceinline__ uint32_t f2tf32(float x) {
    uint32_t r;
    asm("cvt.rna.tf32.f32 %0, %1;" : "=r"(r) : "f"(x));
    return r;
}
// tile rows are 128 B = 8 x 16B columns; swizzle col16 ^= (row & 7)
__device__ __forceinline__ int swz_off(int row, int byte_in_row) {
    const int c16 = byte_in_row >> 4;
    const int sub = byte_in_row & 15;
    return row * 128 + (((c16 ^ (row & 7)) << 4) | sub);
}

#define LDSM_X4(r0, r1, r2, r3, addr)                                          \
    asm volatile("ldmatrix.sync.aligned.m8n8.x4.shared.b16 {%0,%1,%2,%3}, [%4];" \
                 : "=r"(r0), "=r"(r1), "=r"(r2), "=r"(r3) : "r"(addr))

#define MMA_TF32(c, a, b0v, b1v)                                               \
    asm volatile("mma.sync.aligned.m16n8k8.row.col.f32.tf32.tf32.f32 "         \
                 "{%0,%1,%2,%3}, {%4,%5,%6,%7}, {%8,%9}, {%0,%1,%2,%3};"       \
                 : "+f"((c)[0]), "+f"((c)[1]), "+f"((c)[2]), "+f"((c)[3])      \
                 : "r"((a)[0]), "r"((a)[1]), "r"((a)[2]), "r"((a)[3]),         \
                   "r"(b0v), "r"(b1v))

// ---------------------------------------------------------------- loaders --
template <bool KC>
__device__ __forceinline__ void ldg_tile(const float* __restrict__ S, long ld,
                                         int tid, float v[16]) {
    if (KC) {
        const int q  = tid & 7;
        const int r0 = tid >> 3;
#pragma unroll
        for (int i = 0; i < 4; ++i)
            *(float4*)(v + 4 * i) =
                *(const float4*)(S + (long)(r0 + 32 * i) * ld + q * 4);
    } else {
        const int r   = tid & 127;
        const int kq0 = (tid >> 7) * 4;
#pragma unroll
        for (int i = 0; i < 4; ++i) {
            const int k = kq0 + 8 * i;
#pragma unroll
            for (int j = 0; j < 4; ++j)
                v[4 * i + j] = S[(long)(k + j) * ld + r];
        }
    }
}
template <bool KC>
__device__ __forceinline__ void sts_tile(char* tile, int tid, const float v[16]) {
    if (KC) {
        const int q  = tid & 7;
        const int r0 = tid >> 3;
#pragma unroll
        for (int i = 0; i < 4; ++i) {
            uint4 w;
            w.x = f2tf32(v[4 * i + 0]); w.y = f2tf32(v[4 * i + 1]);
            w.z = f2tf32(v[4 * i + 2]); w.w = f2tf32(v[4 * i + 3]);
            *(uint4*)(tile + swz_off(r0 + 32 * i, q * 16)) = w;
        }
    } else {
        const int r   = tid & 127;
        const int kq0 = (tid >> 7) * 4;
#pragma unroll
        for (int i = 0; i < 4; ++i) {
            const int k = kq0 + 8 * i;
            uint4 w;
            w.x = f2tf32(v[4 * i + 0]); w.y = f2tf32(v[4 * i + 1]);
            w.z = f2tf32(v[4 * i + 2]); w.w = f2tf32(v[4 * i + 3]);
            *(uint4*)(tile + swz_off(r, k * 4)) = w;
        }
    }
}

// ------------------------------------------------------------- mma engine --
__device__ __forceinline__ void mma_chunk(uint32_t As, uint32_t Bs,
                                          int wm, int wn, int lane,
                                          float (&acc)[4][4][4]) {
    const int mat  = lane >> 3;
    const int l7   = lane & 7;
    const int arow = (mat & 1) * 8 + l7;
    const int ac16 = (mat >> 1);
    const int brow = (mat >> 1) * 8 + l7;
    const int bc16 = (mat & 1);

    uint32_t abase[4], bbase[2];
#pragma unroll
    for (int mi = 0; mi < 4; ++mi)
        abase[mi] = As + (wm * 64 + mi * 16 + arow) * 128;
#pragma unroll
    for (int bi = 0; bi < 2; ++bi)
        bbase[bi] = Bs + (wn * 32 + bi * 16 + brow) * 128;

#pragma unroll
    for (int ks = 0; ks < 4; ++ks) {
        const uint32_t acol = ((ks * 2 + ac16) ^ l7) << 4;
        const uint32_t bcol = ((ks * 2 + bc16) ^ l7) << 4;
        uint32_t a[4][4];
#pragma unroll
        for (int mi = 0; mi < 4; ++mi)
            LDSM_X4(a[mi][0], a[mi][1], a[mi][2], a[mi][3], abase[mi] + acol);
        uint32_t b[2][4];
#pragma unroll
        for (int bi = 0; bi < 2; ++bi)
            LDSM_X4(b[bi][0], b[bi][1], b[bi][2], b[bi][3], bbase[bi] + bcol);
#pragma unroll
        for (int mi = 0; mi < 4; ++mi)
#pragma unroll
            for (int ni = 0; ni < 4; ++ni)
                MMA_TF32(acc[mi][ni], a[mi],
                         b[ni >> 1][(ni & 1) * 2], b[ni >> 1][(ni & 1) * 2 + 1]);
    }
}

// ------------------------------------------------------------------- body --
// EPI: 0 = plain store, 2 = acc + bias[col] * srow[row]
// BSEG: if nonzero, B chunk base jumps BSEG elements every 512 k (expert seg)
template <int KT, bool AKC, bool BKC, int EPI, long long BSEG>
__device__ __forceinline__ void gemm_body(const float* __restrict__ A, long ldA,
                                          const float* __restrict__ B, long ldB,
                                          const float* __restrict__ bias,
                                          const float* __restrict__ srow,
                                          float* __restrict__ C, long ldC) {
    extern __shared__ __align__(16) char dyn[];

    const int tid  = threadIdx.x;
    const int wid  = tid >> 5;
    const int lane = tid & 31;
    const int wm   = wid >> 2;
    const int wn   = wid & 3;
    const int m0   = blockIdx.y * BM;
    const int n0   = blockIdx.x * BN;

    const uint32_t dynb = smem_u32(dyn);
    const uint32_t base = (dynb + 127u) & ~127u;
    char* tiles = dyn + (base - dynb);

    float acc[4][4][4] = {};
    float va[16], vb[16];

    auto aptr = [&](long k0) {
        return AKC ? (A + (long)m0 * ldA + k0) : (A + k0 * ldA + m0);
    };
    auto bptr = [&](long k0) {
        if (BSEG)
            return B + (k0 >> 9) * BSEG + (long)n0 * ldB + (k0 & 511);
        return BKC ? (B + (long)n0 * ldB + k0) : (B + k0 * ldB + n0);
    };

    // prologue: chunk 0 -> buf0; prefetch chunk 1 into regs
    ldg_tile<AKC>(aptr(0), ldA, tid, va);
    ldg_tile<BKC>(bptr(0), ldB, tid, vb);
    sts_tile<AKC>(tiles, tid, va);
    sts_tile<BKC>(tiles + TILE_BYTES, tid, vb);
    __syncthreads();

    const int NIT = KT / BKT;
    if (NIT > 1) {
        ldg_tile<AKC>(aptr(BKT), ldA, tid, va);
        ldg_tile<BKC>(bptr(BKT), ldB, tid, vb);
    }

    for (int it = 0; it < NIT; ++it) {
        const int cur = it & 1;
        if (it + 1 < NIT) {               // STS-early into the other buffer
            char* nxt = tiles + (cur ^ 1) * 2 * TILE_BYTES;
            sts_tile<AKC>(nxt, tid, va);
            sts_tile<BKC>(nxt + TILE_BYTES, tid, vb);
        }
        mma_chunk(base + cur * 2 * TILE_BYTES,
                  base + cur * 2 * TILE_BYTES + TILE_BYTES,
                  wm, wn, lane, acc);
        if (it + 2 < NIT) {               // LDG chunk it+2
            const long k0 = (long)(it + 2) * BKT;
            ldg_tile<AKC>(aptr(k0), ldA, tid, va);
            ldg_tile<BKC>(bptr(k0), ldB, tid, vb);
        }
        __syncthreads();
    }

    // epilogue
#pragma unroll
    for (int mi = 0; mi < 4; ++mi) {
        const int r0 = m0 + wm * 64 + mi * 16 + (lane >> 2);
        float s0 = 0.f, s1 = 0.f;
        if (EPI == 2) { s0 = __ldg(srow + r0); s1 = __ldg(srow + r0 + 8); }
#pragma unroll
        for (int ni = 0; ni < 4; ++ni) {
            const int c = n0 + wn * 32 + ni * 8 + (lane & 3) * 2;
            float2 v0 = {acc[mi][ni][0], acc[mi][ni][1]};
            float2 v1 = {acc[mi][ni][2], acc[mi][ni][3]};
            if (EPI == 2) {
                const float b0 = __ldg(bias + c), b1 = __ldg(bias + c + 1);
                v0.x += b0 * s0; v0.y += b1 * s0;
                v1.x += b0 * s1; v1.y += b1 * s1;
            }
            *(float2*)(C + (long)r0 * ldC + c)       = v0;
            *(float2*)(C + (long)(r0 + 8) * ldC + c) = v1;
        }
    }
}

// ---------------------------------------------------------------- kernels --
__global__ __launch_bounds__(NTHREADS, 2)
void k1_dispatch(const float* __restrict__ x, const float* __restrict__ dm) {
    const int bz = blockIdx.z, b = bz >> 2, e = bz & 3;
    gemm_body<1024, false, false, 0, 0>(
        dm + (long)b * 1024 * 2048 + e * 512, 2048,   // A: (k=t, m=c) m-contig
        x  + (long)b * 1024 * 2048 + e * 512, 2048,   // B: (k=t, n=i) n-contig
        nullptr, nullptr,
        g_xd + (long)bz * 512 * 512, 512);
}

// rowsum: s[b,t] = sum over 2048 combine values; one warp per row
__global__ __launch_bounds__(256)
void k_rowsum(const float* __restrict__ cmb) {
    const int warp = (blockIdx.x * 256 + threadIdx.x) >> 5;
    const int lane = threadIdx.x & 31;
    if (warp >= 4096) return;
    const float4* p = (const float4*)(cmb + (long)warp * 2048);
    float s = 0.f;
#pragma unroll
    for (int j = 0; j < 16; ++j) {
        const float4 v = p[lane + 32 * j];
        s += (v.x + v.y) + (v.z + v.w);
    }
#pragma unroll
    for (int o = 16; o; o >>= 1) s += __shfl_xor_sync(0xFFFFFFFFu, s, o);
    if (lane == 0) g_s[warp] = s;
}

// z[b,t,e*512+i] = sum_c combine[b,t,e,c] * xd[b,e,c,i]
__global__ __launch_bounds__(NTHREADS, 2)
void k2_z(const float* __restrict__ cmb) {
    const int bz = blockIdx.z, b = bz >> 2, e = bz & 3;
    gemm_body<512, true, false, 0, 0>(
        cmb + (long)b * 1024 * 2048 + e * 512, 2048,  // A: (m=t, k=c) k-contig
        g_xd + (long)bz * 512 * 512, 512,             // B: (k=c, n=i) n-contig
        nullptr, nullptr,
        g_z + (long)b * 1024 * 2048 + e * 512, 2048);
}

// out[b] = z[b] (1024x2048) @ Wseg^T (K=2048, expert-segmented) + bias*s
__global__ __launch_bounds__(NTHREADS, 2)
void k3_out(const float* __restrict__ w, const float* __restrict__ bias,
            float* __restrict__ out) {
    const int b = blockIdx.z;
    gemm_body<2048, true, true, 2, 8192ll * 512>(
        g_z + (long)b * 1024 * 2048, 2048,            // A: (m=t, k) k-contig
        w, 512,                                       // B: w[e,o,i] segmented
        bias, g_s + b * 1024,
        out + (long)b * 1024 * 8192, 8192);
}

// ----------------------------------------------------------------- launch --
extern "C" void kernel_launch(void* const* d_in, const int* in_sizes, int n_in,
                              void* d_out, int out_size) {
    const float* x       = (const float*)d_in[0];
    const float* combine = (const float*)d_in[1];
    const float* dmask   = (const float*)d_in[2];
    const float* weight  = (const float*)d_in[3];
    const float* bias    = (const float*)d_in[4];
    float*       out     = (float*)d_out;

    const int SMEM = 4 * TILE_BYTES + 256;
    cudaFuncSetAttribute(k1_dispatch, cudaFuncAttributeMaxDynamicSharedMemorySize, SMEM);
    cudaFuncSetAttribute(k2_z,        cudaFuncAttributeMaxDynamicSharedMemorySize, SMEM);
    cudaFuncSetAttribute(k3_out,      cudaFuncAttributeMaxDynamicSharedMemorySize, SMEM);

    k1_dispatch<<<dim3(4, 4, 16), NTHREADS, SMEM>>>(x, dmask);
    k_rowsum   <<<512, 256>>>(combine);
    k2_z       <<<dim3(4, 8, 16), NTHREADS, SMEM>>>(combine);
    k3_out     <<<dim3(64, 8, 4), NTHREADS, SMEM>>>(weight, bias, out);
}

// round 12
// speedup vs baseline: 6.1655x; 1.1123x over previous
#include <cuda_runtime.h>
#include <cstdint>

// ---------------------------------------------------------------------------
// ExpertsChooseMaskedExpand — round 10: k3 with 64x64 warp tiles + cp.async
//
//   WC: wt = tf32(weight)                                  (~20 us, 128 MB)
//   K1: xd[b,e] (512x512)   = dispatch^T @ x_e               8.6 GF
//   RS: s[b,t]              = rowsum(combine)                tiny
//   K2: z[b] (1024x2048)    = combine_e @ xd_e  (tf32 out)   8.6 GF
//   K3: out[b] (1024x8192)  = z[b] @ wt_seg^T + bias*s     137.4 GF
//
// K3: CTA 128x256, 8 warps (64x64 each), 3-stage cp.async pipeline,
// K-chunk 32. Operands pre-converted to tf32 bits -> raw 16B async copies,
// no cvt / register staging in the mainloop. MMA-bound by design.
// ---------------------------------------------------------------------------

#define NTHREADS   256
#define BKT        32
#define TILE_BYTES 16384            // 128 rows x 128 B
#define K3_STAGE   49152            // A 16 KB + B 32 KB
#define K3_SMEM    (3 * K3_STAGE + 256)

__device__ float g_xd[16ull * 512 * 512];     // 16 MB  (b*4+e, c, i)  f32
__device__ float g_z [4ull * 1024 * 2048];    // 32 MB  (b, t, e*512+i) tf32 bits
__device__ float g_wt[8192ull * 2048];        // 64 MB  weight, tf32 bits
__device__ float g_s [4 * 1024];              // rowsum of combine

// ---------------------------------------------------------------- helpers --
__device__ __forceinline__ uint32_t smem_u32(const void* p) {
    uint32_t a;
    asm("{ .reg .u64 t; cvta.to.shared.u64 t, %1; cvt.u32.u64 %0, t; }"
        : "=r"(a) : "l"(p));
    return a;
}
__device__ __forceinline__ uint32_t f2tf32(float x) {
    uint32_t r;
    asm("cvt.rna.tf32.f32 %0, %1;" : "=r"(r) : "f"(x));
    return r;
}
// rows are 128 B = 8 x 16B cols; col16 ^= (row & 7)
__device__ __forceinline__ int swz_off(int row, int byte_in_row) {
    const int c16 = byte_in_row >> 4;
    const int sub = byte_in_row & 15;
    return row * 128 + (((c16 ^ (row & 7)) << 4) | sub);
}
__device__ __forceinline__ uint32_t swz16(int row, int q) {      // 16B granule
    return (uint32_t)(row * 128 + ((q ^ (row & 7)) << 4));
}

#define LDSM_X4(r0, r1, r2, r3, addr)                                          \
    asm volatile("ldmatrix.sync.aligned.m8n8.x4.shared.b16 {%0,%1,%2,%3}, [%4];" \
                 : "=r"(r0), "=r"(r1), "=r"(r2), "=r"(r3) : "r"(addr))

#define MMA_TF32(c, a, b0v, b1v)                                               \
    asm volatile("mma.sync.aligned.m16n8k8.row.col.f32.tf32.tf32.f32 "         \
                 "{%0,%1,%2,%3}, {%4,%5,%6,%7}, {%8,%9}, {%0,%1,%2,%3};"       \
                 : "+f"((c)[0]), "+f"((c)[1]), "+f"((c)[2]), "+f"((c)[3])      \
                 : "r"((a)[0]), "r"((a)[1]), "r"((a)[2]), "r"((a)[3]),         \
                   "r"(b0v), "r"(b1v))

#define CP_ASYNC16(dst, src)                                                   \
    asm volatile("cp.async.cg.shared.global [%0], [%1], 16;"                   \
                 :: "r"(dst), "l"(src))
#define CP_COMMIT()  asm volatile("cp.async.commit_group;" ::: "memory")
#define CP_WAIT(n)   asm volatile("cp.async.wait_group %0;" :: "n"(n) : "memory")

// ================= generic engine (k1/k2): unchanged structure ============
template <bool KC>
__device__ __forceinline__ void ldg_tile(const float* __restrict__ S, long ld,
                                         int tid, float v[16]) {
    if (KC) {
        const int q  = tid & 7;
        const int r0 = tid >> 3;
#pragma unroll
        for (int i = 0; i < 4; ++i)
            *(float4*)(v + 4 * i) =
                *(const float4*)(S + (long)(r0 + 32 * i) * ld + q * 4);
    } else {
        const int r   = tid & 127;
        const int kq0 = (tid >> 7) * 4;
#pragma unroll
        for (int i = 0; i < 4; ++i) {
            const int k = kq0 + 8 * i;
#pragma unroll
            for (int j = 0; j < 4; ++j)
                v[4 * i + j] = S[(long)(k + j) * ld + r];
        }
    }
}
template <bool KC>
__device__ __forceinline__ void sts_tile(char* tile, int tid, const float v[16]) {
    if (KC) {
        const int q  = tid & 7;
        const int r0 = tid >> 3;
#pragma unroll
        for (int i = 0; i < 4; ++i) {
            uint4 w;
            w.x = f2tf32(v[4 * i + 0]); w.y = f2tf32(v[4 * i + 1]);
            w.z = f2tf32(v[4 * i + 2]); w.w = f2tf32(v[4 * i + 3]);
            *(uint4*)(tile + swz_off(r0 + 32 * i, q * 16)) = w;
        }
    } else {
        const int r   = tid & 127;
        const int kq0 = (tid >> 7) * 4;
#pragma unroll
        for (int i = 0; i < 4; ++i) {
            const int k = kq0 + 8 * i;
            uint4 w;
            w.x = f2tf32(v[4 * i + 0]); w.y = f2tf32(v[4 * i + 1]);
            w.z = f2tf32(v[4 * i + 2]); w.w = f2tf32(v[4 * i + 3]);
            *(uint4*)(tile + swz_off(r, k * 4)) = w;
        }
    }
}

__device__ __forceinline__ void mma_chunk(uint32_t As, uint32_t Bs,
                                          int wm, int wn, int lane,
                                          float (&acc)[4][4][4]) {
    const int mat  = lane >> 3;
    const int l7   = lane & 7;
    const int arow = (mat & 1) * 8 + l7;
    const int ac16 = (mat >> 1);
    const int brow = (mat >> 1) * 8 + l7;
    const int bc16 = (mat & 1);

    uint32_t abase[4], bbase[2];
#pragma unroll
    for (int mi = 0; mi < 4; ++mi)
        abase[mi] = As + (wm * 64 + mi * 16 + arow) * 128;
#pragma unroll
    for (int bi = 0; bi < 2; ++bi)
        bbase[bi] = Bs + (wn * 32 + bi * 16 + brow) * 128;

#pragma unroll
    for (int ks = 0; ks < 4; ++ks) {
        const uint32_t acol = ((ks * 2 + ac16) ^ l7) << 4;
        const uint32_t bcol = ((ks * 2 + bc16) ^ l7) << 4;
        uint32_t a[4][4];
#pragma unroll
        for (int mi = 0; mi < 4; ++mi)
            LDSM_X4(a[mi][0], a[mi][1], a[mi][2], a[mi][3], abase[mi] + acol);
        uint32_t b[2][4];
#pragma unroll
        for (int bi = 0; bi < 2; ++bi)
            LDSM_X4(b[bi][0], b[bi][1], b[bi][2], b[bi][3], bbase[bi] + bcol);
#pragma unroll
        for (int mi = 0; mi < 4; ++mi)
#pragma unroll
            for (int ni = 0; ni < 4; ++ni)
                MMA_TF32(acc[mi][ni], a[mi],
                         b[ni >> 1][(ni & 1) * 2], b[ni >> 1][(ni & 1) * 2 + 1]);
    }
}

// EPI: 0 = plain f32 store, 1 = store tf32-converted bits
template <int KT, bool AKC, bool BKC, int EPI>
__device__ __forceinline__ void gemm_body(const float* __restrict__ A, long ldA,
                                          const float* __restrict__ B, long ldB,
                                          float* __restrict__ C, long ldC) {
    extern __shared__ __align__(16) char dyn[];

    const int tid  = threadIdx.x;
    const int wid  = tid >> 5;
    const int lane = tid & 31;
    const int wm   = wid >> 2;
    const int wn   = wid & 3;
    const int m0   = blockIdx.y * 128;
    const int n0   = blockIdx.x * 128;

    const uint32_t dynb = smem_u32(dyn);
    const uint32_t base = (dynb + 127u) & ~127u;
    char* tiles = dyn + (base - dynb);

    float acc[4][4][4] = {};
    float va[16], vb[16];

    auto aptr = [&](long k0) {
        return AKC ? (A + (long)m0 * ldA + k0) : (A + k0 * ldA + m0);
    };
    auto bptr = [&](long k0) {
        return BKC ? (B + (long)n0 * ldB + k0) : (B + k0 * ldB + n0);
    };

    ldg_tile<AKC>(aptr(0), ldA, tid, va);
    ldg_tile<BKC>(bptr(0), ldB, tid, vb);
    sts_tile<AKC>(tiles, tid, va);
    sts_tile<BKC>(tiles + TILE_BYTES, tid, vb);
    __syncthreads();

    const int NIT = KT / BKT;
    if (NIT > 1) {
        ldg_tile<AKC>(aptr(BKT), ldA, tid, va);
        ldg_tile<BKC>(bptr(BKT), ldB, tid, vb);
    }

    for (int it = 0; it < NIT; ++it) {
        const int cur = it & 1;
        if (it + 1 < NIT) {
            char* nxt = tiles + (cur ^ 1) * 2 * TILE_BYTES;
            sts_tile<AKC>(nxt, tid, va);
            sts_tile<BKC>(nxt + TILE_BYTES, tid, vb);
        }
        mma_chunk(base + cur * 2 * TILE_BYTES,
                  base + cur * 2 * TILE_BYTES + TILE_BYTES,
                  wm, wn, lane, acc);
        if (it + 2 < NIT) {
            const long k0 = (long)(it + 2) * BKT;
            ldg_tile<AKC>(aptr(k0), ldA, tid, va);
            ldg_tile<BKC>(bptr(k0), ldB, tid, vb);
        }
        __syncthreads();
    }

#pragma unroll
    for (int mi = 0; mi < 4; ++mi) {
        const int r0 = m0 + wm * 64 + mi * 16 + (lane >> 2);
#pragma unroll
        for (int ni = 0; ni < 4; ++ni) {
            const int c = n0 + wn * 32 + ni * 8 + (lane & 3) * 2;
            float2 v0 = {acc[mi][ni][0], acc[mi][ni][1]};
            float2 v1 = {acc[mi][ni][2], acc[mi][ni][3]};
            if (EPI == 1) {
                v0.x = __uint_as_float(f2tf32(v0.x));
                v0.y = __uint_as_float(f2tf32(v0.y));
                v1.x = __uint_as_float(f2tf32(v1.x));
                v1.y = __uint_as_float(f2tf32(v1.y));
            }
            *(float2*)(C + (long)r0 * ldC + c)       = v0;
            *(float2*)(C + (long)(r0 + 8) * ldC + c) = v1;
        }
    }
}

// ---------------------------------------------------------------- kernels --
__global__ __launch_bounds__(NTHREADS, 2)
void k1_dispatch(const float* __restrict__ x, const float* __restrict__ dm) {
    const int bz = blockIdx.z, b = bz >> 2, e = bz & 3;
    gemm_body<1024, false, false, 0>(
        dm + (long)b * 1024 * 2048 + e * 512, 2048,
        x  + (long)b * 1024 * 2048 + e * 512, 2048,
        g_xd + (long)bz * 512 * 512, 512);
}

__global__ __launch_bounds__(256)
void k_rowsum(const float* __restrict__ cmb) {
    const int warp = (blockIdx.x * 256 + threadIdx.x) >> 5;
    const int lane = threadIdx.x & 31;
    if (warp >= 4096) return;
    const float4* p = (const float4*)(cmb + (long)warp * 2048);
    float s = 0.f;
#pragma unroll
    for (int j = 0; j < 16; ++j) {
        const float4 v = p[lane + 32 * j];
        s += (v.x + v.y) + (v.z + v.w);
    }
#pragma unroll
    for (int o = 16; o; o >>= 1) s += __shfl_xor_sync(0xFFFFFFFFu, s, o);
    if (lane == 0) g_s[warp] = s;
}

__global__ __launch_bounds__(256)
void k_wcvt(const float* __restrict__ w) {
    const long i = ((long)blockIdx.x * 256 + threadIdx.x) * 4;
    const float4 v = *(const float4*)(w + i);
    uint4 u;
    u.x = f2tf32(v.x); u.y = f2tf32(v.y); u.z = f2tf32(v.z); u.w = f2tf32(v.w);
    *(uint4*)(g_wt + i) = u;
}

// z (tf32 bits) = combine_e @ xd_e
__global__ __launch_bounds__(NTHREADS, 2)
void k2_z(const float* __restrict__ cmb) {
    const int bz = blockIdx.z, b = bz >> 2, e = bz & 3;
    gemm_body<512, true, false, 1>(
        cmb + (long)b * 1024 * 2048 + e * 512, 2048,
        g_xd + (long)bz * 512 * 512, 512,
        g_z + (long)b * 1024 * 2048 + e * 512, 2048);
}

// ================= k3: CTA 128x256, warp 64x64, cp.async 3-stage ==========
__device__ __forceinline__ void k3_load_stage(uint32_t sbase,
                                              const float* __restrict__ Ak,
                                              const float* __restrict__ Bk,
                                              int tid) {
    const int q  = tid & 7;
    const int r0 = tid >> 3;
#pragma unroll
    for (int i = 0; i < 4; ++i) {          // A: 128 rows x 32 k
        const int r = r0 + 32 * i;
        CP_ASYNC16(sbase + swz16(r, q), (const void*)(Ak + (long)r * 2048 + q * 4));
    }
#pragma unroll
    for (int i = 0; i < 8; ++i) {          // B: 256 rows x 32 k
        const int r = r0 + 32 * i;
        CP_ASYNC16(sbase + 16384 + swz16(r, q),
                   (const void*)(Bk + (long)r * 512 + q * 4));
    }
}

__device__ __forceinline__ void mma_chunk64(uint32_t As, uint32_t Bs,
                                            int wm, int wn, int lane,
                                            float (&acc)[4][8][4]) {
    const int mat  = lane >> 3;
    const int l7   = lane & 7;
    const int arow = (mat & 1) * 8 + l7;
    const int ac16 = (mat >> 1);
    const int brow = (mat >> 1) * 8 + l7;
    const int bc16 = (mat & 1);

    uint32_t abase[4], bbase[4];
#pragma unroll
    for (int mi = 0; mi < 4; ++mi)
        abase[mi] = As + (wm * 64 + mi * 16 + arow) * 128;
#pragma unroll
    for (int bi = 0; bi < 4; ++bi)
        bbase[bi] = Bs + (wn * 64 + bi * 16 + brow) * 128;

#pragma unroll
    for (int ks = 0; ks < 4; ++ks) {
        const uint32_t acol = ((ks * 2 + ac16) ^ l7) << 4;
        const uint32_t bcol = ((ks * 2 + bc16) ^ l7) << 4;
        uint32_t a[4][4];
#pragma unroll
        for (int mi = 0; mi < 4; ++mi)
            LDSM_X4(a[mi][0], a[mi][1], a[mi][2], a[mi][3], abase[mi] + acol);
        uint32_t b[4][4];
#pragma unroll
        for (int bi = 0; bi < 4; ++bi)
            LDSM_X4(b[bi][0], b[bi][1], b[bi][2], b[bi][3], bbase[bi] + bcol);
#pragma unroll
        for (int mi = 0; mi < 4; ++mi)
#pragma unroll
            for (int ni = 0; ni < 8; ++ni)
                MMA_TF32(acc[mi][ni], a[mi],
                         b[ni >> 1][(ni & 1) * 2], b[ni >> 1][(ni & 1) * 2 + 1]);
    }
}

__global__ __launch_bounds__(256, 1)
void k3_out(const float* __restrict__ bias, float* __restrict__ out) {
    const int b   = blockIdx.z;
    const int m0  = blockIdx.y * 128;
    const int n0  = blockIdx.x * 256;
    const int tid  = threadIdx.x;
    const int wid  = tid >> 5;
    const int lane = tid & 31;
    const int wm   = wid >> 2;
    const int wn   = wid & 3;

    extern __shared__ __align__(16) char dyn[];
    const uint32_t dynb = smem_u32(dyn);
    const uint32_t base = (dynb + 127u) & ~127u;

    const float* Ab = g_z + (long)b * 1024 * 2048 + (long)m0 * 2048;
    auto bkp = [&](int k0) {
        return g_wt + (long)(k0 >> 9) * (8192 * 512) + (long)n0 * 512 + (k0 & 511);
    };

    float acc[4][8][4] = {};

    k3_load_stage(base, Ab, bkp(0), tid);                   CP_COMMIT();
    k3_load_stage(base + K3_STAGE, Ab + 32, bkp(32), tid);  CP_COMMIT();

    const int NIT = 64;                  // K = 2048
    for (int it = 0; it < NIT; ++it) {
        if (it + 2 < NIT) { CP_WAIT(1); } else { CP_WAIT(0); }
        __syncthreads();                 // stage it resident; reads of it-1 done
        if (it + 2 < NIT) {
            const int k0 = (it + 2) * BKT;
            k3_load_stage(base + ((it + 2) % 3) * K3_STAGE, Ab + k0, bkp(k0), tid);
            CP_COMMIT();
        }
        const uint32_t st = base + (it % 3) * K3_STAGE;
        mma_chunk64(st, st + 16384, wm, wn, lane, acc);
    }

    // epilogue: + bias[col] * s[row]
#pragma unroll
    for (int mi = 0; mi < 4; ++mi) {
        const int r  = m0 + wm * 64 + mi * 16 + (lane >> 2);
        const float s0 = __ldg(g_s + b * 1024 + r);
        const float s1 = __ldg(g_s + b * 1024 + r + 8);
        float* row0 = out + ((long)b * 1024 + r) * 8192;
#pragma unroll
        for (int ni = 0; ni < 8; ++ni) {
            const int c = n0 + wn * 64 + ni * 8 + (lane & 3) * 2;
            const float b0 = __ldg(bias + c), b1 = __ldg(bias + c + 1);
            float2 v0 = {acc[mi][ni][0] + b0 * s0, acc[mi][ni][1] + b1 * s0};
            float2 v1 = {acc[mi][ni][2] + b0 * s1, acc[mi][ni][3] + b1 * s1};
            *(float2*)(row0 + c)          = v0;
            *(float2*)(row0 + 8 * 8192 + c) = v1;
        }
    }
}

// ----------------------------------------------------------------- launch --
extern "C" void kernel_launch(void* const* d_in, const int* in_sizes, int n_in,
                              void* d_out, int out_size) {
    const float* x       = (const float*)d_in[0];
    const float* combine = (const float*)d_in[1];
    const float* dmask   = (const float*)d_in[2];
    const float* weight  = (const float*)d_in[3];
    const float* bias    = (const float*)d_in[4];
    float*       out     = (float*)d_out;

    const int SMEM12 = 4 * TILE_BYTES + 256;
    cudaFuncSetAttribute(k1_dispatch, cudaFuncAttributeMaxDynamicSharedMemorySize, SMEM12);
    cudaFuncSetAttribute(k2_z,        cudaFuncAttributeMaxDynamicSharedMemorySize, SMEM12);
    cudaFuncSetAttribute(k3_out,      cudaFuncAttributeMaxDynamicSharedMemorySize, K3_SMEM);

    k_wcvt     <<<8192 * 2048 / 1024, 256>>>(weight);
    k1_dispatch<<<dim3(4, 4, 16), NTHREADS, SMEM12>>>(x, dmask);
    k_rowsum   <<<512, 256>>>(combine);
    k2_z       <<<dim3(4, 8, 16), NTHREADS, SMEM12>>>(combine);
    k3_out     <<<dim3(32, 8, 4), 256, K3_SMEM>>>(bias, out);
}